// round 15
// baseline (speedup 1.0000x reference)
#include <cuda_runtime.h>
#include <cuda_bf16.h>

#define B_    256
#define T_    192
#define E_    300
#define H_    128
#define G4    512
#define V_    11626
#define NT_   13
#define H2_   256
#define NEGV  (-10000.0f)
#define START_ 0
#define STOP_  10

#define VPAD  11648           // 91 * 128
#define KP    304             // K padded to 16
#define PCHB  384             // projmm smem row pitch bytes (24 chunks)
#define PTILE 49152           // 128 * PCHB
#define PSMEM (2 * PTILE + 512)

typedef unsigned long long ull;

// ---- device scratch (allocations are forbidden) ----
__device__ float          g_projP[2][(size_t)V_ * G4];   // unit-major: col = 4u+gate
__device__ __nv_bfloat16  g_WA[2][G4 * H_];              // lstm A-matrix [m'][k]
__device__ __nv_bfloat16  g_WB[2][G4 * KP];              // proj B-matrix [c'][k]
__device__ __nv_bfloat16  g_embB[(size_t)VPAD * KP];     // emb bf16 padded
__device__ __nv_bfloat16  g_hbuf[(size_t)B_ * T_ * H2_];
__device__ float          g_feats[(size_t)B_ * T_ * NT_];
__device__ float          g_nll[B_];
__device__ int            g_perm[B_];

__device__ __forceinline__ float tanh_mufu(float x) {
    float r; asm("tanh.approx.f32 %0, %1;" : "=f"(r) : "f"(x)); return r;
}
__device__ __forceinline__ float sig_mufu(float x) {
    return fmaf(tanh_mufu(0.5f * x), 0.5f, 0.5f);
}

// ---- tensor-core helpers ----
__device__ __forceinline__ void ldsm4(unsigned addr, unsigned& r0, unsigned& r1,
                                      unsigned& r2, unsigned& r3) {
    asm volatile("ldmatrix.sync.aligned.m8n8.x4.shared.b16 {%0,%1,%2,%3}, [%4];"
                 : "=r"(r0), "=r"(r1), "=r"(r2), "=r"(r3) : "r"(addr));
}
__device__ __forceinline__ void ldsm4t(unsigned addr, unsigned& r0, unsigned& r1,
                                       unsigned& r2, unsigned& r3) {
    asm volatile("ldmatrix.sync.aligned.m8n8.x4.trans.shared.b16 {%0,%1,%2,%3}, [%4];"
                 : "=r"(r0), "=r"(r1), "=r"(r2), "=r"(r3) : "r"(addr));
}
__device__ __forceinline__ void mma16816(float* d, unsigned a0, unsigned a1,
                                         unsigned a2, unsigned a3,
                                         unsigned b0, unsigned b1) {
    asm volatile("mma.sync.aligned.m16n8k16.row.col.f32.bf16.bf16.f32 "
                 "{%0,%1,%2,%3}, {%4,%5,%6,%7}, {%8,%9}, {%0,%1,%2,%3};"
                 : "+f"(d[0]), "+f"(d[1]), "+f"(d[2]), "+f"(d[3])
                 : "r"(a0), "r"(a1), "r"(a2), "r"(a3), "r"(b0), "r"(b1));
}

// ---- block 0: rank sort by clamped length; other blocks: zero hbuf ----
__global__ void __launch_bounds__(256) k_sortzero(const int* __restrict__ seqlen) {
    if (blockIdx.x == 0) {
        __shared__ int len_sh[B_];
        int t = threadIdx.x;
        int L = seqlen[t];
        L = L < 1 ? 1 : (L > T_ ? T_ : L);
        len_sh[t] = L;
        __syncthreads();
        int rank = 0;
        for (int i = 0; i < B_; i++) {
            int Li = len_sh[i];
            rank += (Li < L) || (Li == L && i < t);
        }
        g_perm[rank] = t;
    } else {
        size_t nh = (size_t)B_ * T_ * H2_ * 2 / 16;      // uint4 count
        size_t stride = (size_t)(gridDim.x - 1) * blockDim.x;
        size_t i = (size_t)(blockIdx.x - 1) * blockDim.x + threadIdx.x;
        uint4 zu = make_uint4(0u, 0u, 0u, 0u);
        for (; i < nh; i += stride) ((uint4*)g_hbuf)[i] = zu;
    }
}

// ---- one pack kernel: emb -> bf16, W_ih -> g_WB (permuted), W_hh -> g_WA ----
__global__ void k_packall(const float* __restrict__ emb,
                          const float* __restrict__ Wihf, const float* __restrict__ Wihb,
                          const float* __restrict__ Whhf, const float* __restrict__ Whhb) {
    size_t idx = (size_t)blockIdx.x * 256 + threadIdx.x;
    if (idx < (size_t)VPAD * KP) {
        int v = (int)(idx / KP), e = (int)(idx % KP);
        float x = (v < V_ && e < E_) ? emb[(size_t)v * E_ + e] : 0.f;
        g_embB[idx] = __float2bfloat16(x);
    }
    if (idx < 2 * G4 * KP) {
        int d = (int)(idx / (G4 * KP)), rem = (int)(idx % (G4 * KP));
        int c = rem / KP, k = rem % KP;
        const float* W = d ? Wihb : Wihf;
        int orow = (c & 3) * 128 + (c >> 2);
        g_WB[d][c * KP + k] = __float2bfloat16(k < E_ ? W[orow * E_ + k] : 0.f);
    }
    if (idx < 2 * G4 * H_) {
        int d = (int)(idx / (G4 * H_)), rem = (int)(idx % (G4 * H_));
        int n = rem >> 7, k = rem & 127;
        const float* W = d ? Whhb : Whhf;
        int gate = n >> 7, u = n & 127;
        int mp = 32 * (u >> 3) + (u & 7) + 8 * gate;
        g_WA[d][mp * H_ + k] = __float2bfloat16(W[n * H_ + k]);
    }
}

// ---- proj GEMM via HMMA, K split into 2 passes (96 KB smem -> 2 CTA/SM) ----
__global__ void __launch_bounds__(256) k_projmm(const float* __restrict__ bf,
                                                const float* __restrict__ bb) {
    extern __shared__ __align__(16) char ps[];
    const int d  = blockIdx.z;
    const int m0 = blockIdx.x * 128;
    const int n0 = blockIdx.y * 128;
    const float* bias = d ? bb : bf;
    const int tid = threadIdx.x;
    const int w = tid >> 5, lane = tid & 31;
    float* bsh = (float*)(ps + 2 * PTILE);

    if (tid < 128) {
        int c = n0 + tid;
        bsh[tid] = bias[(c & 3) * 128 + (c >> 2)];
    }

    const int wm = w >> 2, wn = w & 3;
    float acc[4][4][4];
#pragma unroll
    for (int mt = 0; mt < 4; mt++)
#pragma unroll
        for (int nt = 0; nt < 4; nt++)
#pragma unroll
            for (int q = 0; q < 4; q++) acc[mt][nt][q] = 0.f;

    const unsigned psu = (unsigned)__cvta_generic_to_shared(ps);
    const unsigned aAddr = psu + (wm * 64 + (lane & 15)) * PCHB;
    const unsigned axor = lane & 7;
    const unsigned acs  = lane >> 4;
    const int bn = wn * 32 + (lane & 7) + ((lane >> 4) << 3);
    const unsigned bAddr = psu + PTILE + bn * PCHB;
    const unsigned bcs  = (lane >> 3) & 1;

    const uint4* srcA = (const uint4*)(g_embB + (size_t)m0 * KP);
    const uint4* srcW = (const uint4*)(g_WB[d] + (size_t)n0 * KP);

#pragma unroll
    for (int pass = 0; pass < 2; pass++) {
        const int nch = pass ? 18 : 20;
        const int cbase = pass * 20;
        if (pass) __syncthreads();
        for (int i = tid; i < 128 * nch; i += 256) {
            int row = i / nch, ch = i % nch;
            unsigned off = row * PCHB + (((unsigned)ch ^ (row & 7)) << 4);
            *(uint4*)(ps + off)         = srcA[row * 38 + cbase + ch];
            *(uint4*)(ps + PTILE + off) = srcW[row * 38 + cbase + ch];
        }
        __syncthreads();
        const int nkt = pass ? 9 : 10;
        for (int kt = 0; kt < nkt; kt++) {
            unsigned a[4][4];
            unsigned aoff = ((((unsigned)(2 * kt) + acs) ^ axor) << 4);
#pragma unroll
            for (int mt = 0; mt < 4; mt++)
                ldsm4(aAddr + mt * 16 * PCHB + aoff, a[mt][0], a[mt][1], a[mt][2], a[mt][3]);
            unsigned bq[2][4];
            unsigned boff = ((((unsigned)(2 * kt) + bcs) ^ axor) << 4);
#pragma unroll
            for (int nb = 0; nb < 2; nb++)
                ldsm4(bAddr + nb * 16 * PCHB + boff, bq[nb][0], bq[nb][1], bq[nb][2], bq[nb][3]);
#pragma unroll
            for (int mt = 0; mt < 4; mt++) {
                mma16816(acc[mt][0], a[mt][0], a[mt][1], a[mt][2], a[mt][3], bq[0][0], bq[0][1]);
                mma16816(acc[mt][1], a[mt][0], a[mt][1], a[mt][2], a[mt][3], bq[0][2], bq[0][3]);
                mma16816(acc[mt][2], a[mt][0], a[mt][1], a[mt][2], a[mt][3], bq[1][0], bq[1][1]);
                mma16816(acc[mt][3], a[mt][0], a[mt][1], a[mt][2], a[mt][3], bq[1][2], bq[1][3]);
            }
        }
    }

#pragma unroll
    for (int mt = 0; mt < 4; mt++) {
        int r = m0 + wm * 64 + mt * 16 + (lane >> 2);
#pragma unroll
        for (int nt = 0; nt < 4; nt++) {
            int cl = wn * 32 + nt * 8 + 2 * (lane & 3);
            float b0 = bsh[cl], b1 = bsh[cl + 1];
            float* dst = &g_projP[d][(size_t)r * G4 + n0 + cl];
            if (r < V_)
                *(float2*)dst = make_float2(acc[mt][nt][0] + b0, acc[mt][nt][1] + b1);
            if (r + 8 < V_)
                *(float2*)(dst + 8 * G4) = make_float2(acc[mt][nt][2] + b0, acc[mt][nt][3] + b1);
        }
    }
}

// ---- BiLSTM via transposed HMMA (W in regs), prefetch, split chains ----
__global__ void __launch_bounds__(512) k_lstm(const int* __restrict__ sent,
                                              const int* __restrict__ seqlen) {
    const int d  = blockIdx.y;
    const int g8 = blockIdx.x * 8;
    __shared__ __align__(16) __nv_bfloat16 hsm[2][H_][8];
    __shared__ int toks[8][T_];
    __shared__ int len[8];
    __shared__ int rws[8];

    const int tid = threadIdx.x;
    const int w = tid >> 5, lane = tid & 31;

    ((ull*)hsm)[tid] = 0ull;
    if (tid < 8) {
        int row = g_perm[g8 + tid];
        rws[tid] = row;
        int L = seqlen[row];
        len[tid] = L < 1 ? 1 : (L > T_ ? T_ : L);
    }
    __syncthreads();
    for (int i = tid; i < 8 * T_; i += 512) {
        int r = i / T_, t = i % T_;
        toks[r][t] = sent[rws[r] * T_ + t];
    }
    __syncthreads();

    const int Lmax = len[7];

    unsigned afr[2][8][4];
    {
        const __nv_bfloat16* WA = g_WA[d];
        int mbase = 32 * w + (lane >> 2);
        int kbase = 2 * (lane & 3);
#pragma unroll
        for (int tt = 0; tt < 2; tt++)
#pragma unroll
            for (int kt = 0; kt < 8; kt++) {
                int m = mbase + 16 * tt;
                int k = 16 * kt + kbase;
                afr[tt][kt][0] = *(const unsigned*)&WA[m * H_ + k];
                afr[tt][kt][1] = *(const unsigned*)&WA[(m + 8) * H_ + k];
                afr[tt][kt][2] = *(const unsigned*)&WA[m * H_ + k + 8];
                afr[tt][kt][3] = *(const unsigned*)&WA[(m + 8) * H_ + k + 8];
            }
    }

    const int r0 = 2 * (lane & 3), r1 = r0 + 1;
    const int u  = 8 * w + (lane >> 2);
    const int len0 = len[r0], len1 = len[r1];
    const size_t row0 = (size_t)rws[r0], row1 = (size_t)rws[r1];
    float c0 = 0.f, c1 = 0.f, h0 = 0.f, h1 = 0.f;

    const float4* __restrict__ projP4 = (const float4*)g_projP[d];
    const unsigned hbase = (unsigned)__cvta_generic_to_shared(&hsm[0][0][0]);
    const unsigned ld4_off = (lane & 15) * 16 + ((lane >> 4) << 8);
    const unsigned sts_off = u * 16 + r0 * 2;

    // prefetch proj for t = 0
    float4 pa0, pa1;
    {
        int tt0 = (d == 0) ? 0 : (len0 - 1);
        int tt1 = (d == 0) ? 0 : (len1 - 1);
        pa0 = __ldcg(&projP4[(size_t)toks[r0][tt0] * 128 + u]);
        pa1 = __ldcg(&projP4[(size_t)toks[r1][tt1] * 128 + u]);
    }

    for (int t = 0; t < Lmax; t++) {
        const bool m0 = t < len0, m1 = t < len1;
        // prefetch proj for t+1
        float4 pn0, pn1;
        {
            int tn = (t + 1 < Lmax) ? t + 1 : 0;
            bool n0 = tn < len0, n1 = tn < len1;
            int tt0 = (d == 0) ? tn : (n0 ? (len0 - 1 - tn) : tn);
            int tt1 = (d == 0) ? tn : (n1 ? (len1 - 1 - tn) : tn);
            pn0 = __ldcg(&projP4[(size_t)toks[r0][tt0] * 128 + u]);
            pn1 = __ldcg(&projP4[(size_t)toks[r1][tt1] * 128 + u]);
        }

        float d0[4] = {0.f, 0.f, 0.f, 0.f};
        float d1[4] = {0.f, 0.f, 0.f, 0.f};
        float e0[4] = {0.f, 0.f, 0.f, 0.f};
        float e1[4] = {0.f, 0.f, 0.f, 0.f};
        unsigned hb = hbase + (t & 1) * 2048 + ld4_off;
#pragma unroll
        for (int kt2 = 0; kt2 < 4; kt2++) {
            unsigned b0, b1, b2, b3;
            ldsm4t(hb + kt2 * 512, b0, b1, b2, b3);
            mma16816(d0, afr[0][2*kt2][0],   afr[0][2*kt2][1],   afr[0][2*kt2][2],   afr[0][2*kt2][3],   b0, b1);
            mma16816(d1, afr[1][2*kt2][0],   afr[1][2*kt2][1],   afr[1][2*kt2][2],   afr[1][2*kt2][3],   b0, b1);
            mma16816(e0, afr[0][2*kt2+1][0], afr[0][2*kt2+1][1], afr[0][2*kt2+1][2], afr[0][2*kt2+1][3], b2, b3);
            mma16816(e1, afr[1][2*kt2+1][0], afr[1][2*kt2+1][1], afr[1][2*kt2+1][2], afr[1][2*kt2+1][3], b2, b3);
        }

        {
            float xi = (d0[0] + e0[0]) + pa0.x, xf = (d0[2] + e0[2]) + pa0.y;
            float xg = (d1[0] + e1[0]) + pa0.z, xo = (d1[2] + e1[2]) + pa0.w;
            float si = sig_mufu(xi), sf = sig_mufu(xf), so = sig_mufu(xo);
            float tg = tanh_mufu(xg);
            float cn = sf * c0 + si * tg;
            float hn = so * tanh_mufu(cn);
            c0 = m0 ? cn : c0;
            h0 = m0 ? hn : h0;
        }
        {
            float xi = (d0[1] + e0[1]) + pa1.x, xf = (d0[3] + e0[3]) + pa1.y;
            float xg = (d1[1] + e1[1]) + pa1.z, xo = (d1[3] + e1[3]) + pa1.w;
            float si = sig_mufu(xi), sf = sig_mufu(xf), so = sig_mufu(xo);
            float tg = tanh_mufu(xg);
            float cn = sf * c1 + si * tg;
            float hn = so * tanh_mufu(cn);
            c1 = m1 ? cn : c1;
            h1 = m1 ? hn : h1;
        }
        unsigned hpack = (unsigned)__bfloat16_as_ushort(__float2bfloat16(h0)) |
                         ((unsigned)__bfloat16_as_ushort(__float2bfloat16(h1)) << 16);
        *(unsigned*)((char*)hsm + ((t + 1) & 1) * 2048 + sts_off) = hpack;
        if (m0) {
            int op = (d == 0) ? t : (len0 - 1 - t);
            g_hbuf[(row0 * T_ + op) * H2_ + d * H_ + u] = __float2bfloat16(h0);
        }
        if (m1) {
            int op = (d == 0) ? t : (len1 - 1 - t);
            g_hbuf[(row1 * T_ + op) * H2_ + d * H_ + u] = __float2bfloat16(h1);
        }
        pa0 = pn0;
        pa1 = pn1;
        __syncthreads();
    }
}

// ---- FC: feats = hbuf(bf16) @ W_fc^T; 32 positions/block, warp per tag ----
__global__ void __launch_bounds__(416) k_fc(const float* __restrict__ Wfc) {
    __shared__ uint4 hsm[32][33];
    __shared__ float Wsh[NT_][256];
    int tid = threadIdx.x;
    size_t base = (size_t)blockIdx.x * 32;
    for (int i = tid; i < 32 * 32; i += 416) {
        int p = i >> 5, c = i & 31;
        hsm[p][c] = ((const uint4*)g_hbuf)[(base + p) * 32 + c];
    }
    for (int i = tid; i < NT_ * H2_; i += 416) Wsh[i >> 8][i & 255] = Wfc[i];
    __syncthreads();
    int w = tid >> 5, lane = tid & 31;
    if (w < NT_) {
        float acc = 0.f;
        const float* wr = Wsh[w];
#pragma unroll 4
        for (int c = 0; c < 32; c++) {
            uint4 v = hsm[lane][c];
            const unsigned* vu = (const unsigned*)&v;
#pragma unroll
            for (int e = 0; e < 4; e++) {
                unsigned uu = vu[e];
                float f0 = __uint_as_float(uu << 16);
                float f1 = __uint_as_float(uu & 0xFFFF0000u);
                acc = fmaf(f0, wr[c * 8 + 2 * e], acc);
                acc = fmaf(f1, wr[c * 8 + 2 * e + 1], acc);
            }
        }
        g_feats[(base + lane) * NT_ + w] = acc;
    }
}

// ---- CRF: exp-factorized logsumexp, 1-shfl shift, warp per sequence ----
__global__ void __launch_bounds__(128) k_crf(const float* __restrict__ trans,
                                             const int* __restrict__ tags,
                                             const float* __restrict__ bfc) {
    __shared__ float tr[NT_ * NT_];
    __shared__ float bsh[16];
    int tid = threadIdx.x;
    if (tid < NT_ * NT_) tr[tid] = trans[tid];
    if (tid < NT_) bsh[tid] = bfc[tid];
    __syncthreads();
    int warp = tid >> 5, lane = tid & 31;
    int b = blockIdx.x * 4 + warp;
    bool valid = lane < NT_;
    int jj = valid ? lane : 0;
    float Ej[NT_];
#pragma unroll
    for (int i = 0; i < NT_; i++) Ej[i] = valid ? __expf(tr[jj * NT_ + i]) : 0.f;
    float bj = bsh[jj];
    float alpha = valid ? ((jj == START_) ? 0.f : NEGV) : -3e38f;
    const float* __restrict__ fF = &g_feats[(size_t)b * T_ * NT_];

    for (int t = 0; t < T_; t++) {
        float ft = valid ? (fF[t * NT_ + jj] + bj) : 0.f;
        // shift = max(alpha_0, alpha_1): exact lse shift-invariance; bounded spread
        float sA = __shfl_sync(0xffffffffu, alpha, 0);
        float sB = __shfl_sync(0xffffffffu, alpha, 1);
        float shift = fmaxf(sA, sB);
        float ea = valid ? __expf(alpha - shift) : 0.f;
        float s = 0.f;
#pragma unroll
        for (int i = 0; i < NT_; i++)
            s = fmaf(__shfl_sync(0xffffffffu, ea, i), Ej[i], s);
        float an = shift + __logf(s) + ft;
        if (valid) alpha = an;
    }
    float v = valid ? (alpha + tr[STOP_ * NT_ + jj]) : -3e38f;
    float mm = v;
#pragma unroll
    for (int off = 16; off; off >>= 1) mm = fmaxf(mm, __shfl_xor_sync(0xffffffffu, mm, off));
    float se = valid ? __expf(v - mm) : 0.f;
#pragma unroll
    for (int off = 16; off; off >>= 1) se += __shfl_xor_sync(0xffffffffu, se, off);
    float fwd = mm + __logf(se);

    float gold = 0.f;
    for (int t = lane; t < T_; t += 32) {
        int tg = tags[b * T_ + t];
        int tp = (t == 0) ? START_ : tags[b * T_ + t - 1];
        gold += tr[tg * NT_ + tp] + fF[t * NT_ + tg] + bsh[tg];
    }
#pragma unroll
    for (int off = 16; off; off >>= 1) gold += __shfl_xor_sync(0xffffffffu, gold, off);
    if (lane == 0) {
        int tlast = tags[b * T_ + T_ - 1];
        gold += tr[STOP_ * NT_ + tlast];
        g_nll[b] = fwd - gold;
    }
}

__global__ void k_reduce(float* __restrict__ out) {
    __shared__ float sm[256];
    int tid = threadIdx.x;
    sm[tid] = g_nll[tid];
    __syncthreads();
    for (int s = 128; s > 0; s >>= 1) {
        if (tid < s) sm[tid] += sm[tid + s];
        __syncthreads();
    }
    if (tid == 0) out[0] = sm[0] * (1.f / (float)B_);
}

extern "C" void kernel_launch(void* const* d_in, const int* in_sizes, int n_in,
                              void* d_out, int out_size) {
    const int*   sentence  = (const int*)d_in[0];
    const int*   seq_len   = (const int*)d_in[1];
    const int*   tags      = (const int*)d_in[2];
    const float* embedding = (const float*)d_in[3];
    const float* W_ih_f    = (const float*)d_in[4];
    const float* W_hh_f    = (const float*)d_in[5];
    const float* b_f       = (const float*)d_in[6];
    const float* W_ih_b    = (const float*)d_in[7];
    const float* W_hh_b    = (const float*)d_in[8];
    const float* b_b       = (const float*)d_in[9];
    const float* W_fc      = (const float*)d_in[10];
    const float* b_fc      = (const float*)d_in[11];
    const float* trans     = (const float*)d_in[12];

    cudaFuncSetAttribute(k_projmm, cudaFuncAttributeMaxDynamicSharedMemorySize, PSMEM);

    k_sortzero<<<257, 256>>>(seq_len);                                       // 0
    k_packall<<<(int)(((size_t)VPAD * KP + 255) / 256), 256>>>(
        embedding, W_ih_f, W_ih_b, W_hh_f, W_hh_b);                          // 1
    dim3 gpm(VPAD / 128, 4, 2);
    k_projmm<<<gpm, 256, PSMEM>>>(b_f, b_b);                                 // 2
    dim3 gl(32, 2);
    k_lstm<<<gl, 512>>>(sentence, seq_len);                                  // 3 <- profiled
    k_fc<<<(B_ * T_) / 32, 416>>>(W_fc);                                     // 4
    k_crf<<<B_ / 4, 128>>>(trans, tags, b_fc);                               // 5
    k_reduce<<<1, 256>>>((float*)d_out);                                     // 6
}

// round 16
// speedup vs baseline: 1.5015x; 1.5015x over previous
#include <cuda_runtime.h>
#include <cuda_bf16.h>

#define B_    256
#define T_    192
#define E_    300
#define H_    128
#define G4    512
#define V_    11626
#define NT_   13
#define H2_   256
#define NEGV  (-10000.0f)
#define START_ 0
#define STOP_  10

#define VPAD  11648           // 91 * 128
#define KP    304             // K padded to 16
#define PCHB  384             // projmm smem row pitch bytes (24 chunks)
#define PTILE 49152           // 128 * PCHB
#define PSMEM (2 * PTILE + 512)

typedef unsigned long long ull;

// ---- device scratch (allocations are forbidden) ----
__device__ float          g_projP[2][(size_t)V_ * G4];   // unit-major: col = 4u+gate
__device__ __nv_bfloat16  g_WA[2][G4 * H_];              // lstm A-matrix [m'][k]
__device__ __nv_bfloat16  g_WB[2][G4 * KP];              // proj B-matrix [c'][k]
__device__ __nv_bfloat16  g_embB[(size_t)VPAD * KP];     // emb bf16 padded
__device__ __nv_bfloat16  g_hbuf[(size_t)B_ * T_ * H2_];
__device__ float          g_feats[(size_t)B_ * T_ * NT_];
__device__ float          g_nll[B_];
__device__ int            g_perm[B_];

__device__ __forceinline__ float tanh_mufu(float x) {
    float r; asm("tanh.approx.f32 %0, %1;" : "=f"(r) : "f"(x)); return r;
}
__device__ __forceinline__ float sig_mufu(float x) {
    return fmaf(tanh_mufu(0.5f * x), 0.5f, 0.5f);
}

// ---- tensor-core helpers ----
__device__ __forceinline__ void ldsm4(unsigned addr, unsigned& r0, unsigned& r1,
                                      unsigned& r2, unsigned& r3) {
    asm volatile("ldmatrix.sync.aligned.m8n8.x4.shared.b16 {%0,%1,%2,%3}, [%4];"
                 : "=r"(r0), "=r"(r1), "=r"(r2), "=r"(r3) : "r"(addr));
}
__device__ __forceinline__ void ldsm2t(unsigned addr, unsigned& b0, unsigned& b1) {
    asm volatile("ldmatrix.sync.aligned.m8n8.x2.trans.shared.b16 {%0,%1}, [%2];"
                 : "=r"(b0), "=r"(b1) : "r"(addr));
}
__device__ __forceinline__ void mma16816(float* d, unsigned a0, unsigned a1,
                                         unsigned a2, unsigned a3,
                                         unsigned b0, unsigned b1) {
    asm volatile("mma.sync.aligned.m16n8k16.row.col.f32.bf16.bf16.f32 "
                 "{%0,%1,%2,%3}, {%4,%5,%6,%7}, {%8,%9}, {%0,%1,%2,%3};"
                 : "+f"(d[0]), "+f"(d[1]), "+f"(d[2]), "+f"(d[3])
                 : "r"(a0), "r"(a1), "r"(a2), "r"(a3), "r"(b0), "r"(b1));
}

// ---- merged: block 0 sorts; blocks 1..256 zero hbuf; blocks 257+ pack ----
__global__ void __launch_bounds__(256) k_sortpack(const int* __restrict__ seqlen,
                          const float* __restrict__ emb,
                          const float* __restrict__ Wihf, const float* __restrict__ Wihb,
                          const float* __restrict__ Whhf, const float* __restrict__ Whhb) {
    if (blockIdx.x == 0) {
        __shared__ int len_sh[B_];
        int t = threadIdx.x;
        int L = seqlen[t];
        L = L < 1 ? 1 : (L > T_ ? T_ : L);
        len_sh[t] = L;
        __syncthreads();
        int rank = 0;
        for (int i = 0; i < B_; i++) {
            int Li = len_sh[i];
            rank += (Li < L) || (Li == L && i < t);
        }
        g_perm[rank] = t;
    } else if (blockIdx.x <= 256) {
        size_t nh = (size_t)B_ * T_ * H2_ * 2 / 16;      // uint4 count
        size_t stride = (size_t)256 * 256;
        size_t i = (size_t)(blockIdx.x - 1) * 256 + threadIdx.x;
        uint4 zu = make_uint4(0u, 0u, 0u, 0u);
        for (; i < nh; i += stride) ((uint4*)g_hbuf)[i] = zu;
    } else {
        size_t idx = (size_t)(blockIdx.x - 257) * 256 + threadIdx.x;
        if (idx < (size_t)VPAD * KP) {
            int v = (int)(idx / KP), e = (int)(idx % KP);
            float x = (v < V_ && e < E_) ? emb[(size_t)v * E_ + e] : 0.f;
            g_embB[idx] = __float2bfloat16(x);
        }
        if (idx < 2 * G4 * KP) {
            int d = (int)(idx / (G4 * KP)), rem = (int)(idx % (G4 * KP));
            int c = rem / KP, k = rem % KP;
            const float* W = d ? Wihb : Wihf;
            int orow = (c & 3) * 128 + (c >> 2);
            g_WB[d][c * KP + k] = __float2bfloat16(k < E_ ? W[orow * E_ + k] : 0.f);
        }
        if (idx < 2 * G4 * H_) {
            int d = (int)(idx / (G4 * H_)), rem = (int)(idx % (G4 * H_));
            int n = rem >> 7, k = rem & 127;
            const float* W = d ? Whhb : Whhf;
            int gate = n >> 7, u = n & 127;
            int mp = 32 * (u >> 3) + (u & 7) + 8 * gate;
            g_WA[d][mp * H_ + k] = __float2bfloat16(W[n * H_ + k]);
        }
    }
}

// ---- proj GEMM via HMMA, K split into 2 passes (96 KB smem -> 2 CTA/SM) ----
__global__ void __launch_bounds__(256) k_projmm(const float* __restrict__ bf,
                                                const float* __restrict__ bb) {
    extern __shared__ __align__(16) char ps[];
    const int d  = blockIdx.z;
    const int m0 = blockIdx.x * 128;
    const int n0 = blockIdx.y * 128;
    const float* bias = d ? bb : bf;
    const int tid = threadIdx.x;
    const int w = tid >> 5, lane = tid & 31;
    float* bsh = (float*)(ps + 2 * PTILE);

    if (tid < 128) {
        int c = n0 + tid;
        bsh[tid] = bias[(c & 3) * 128 + (c >> 2)];
    }

    const int wm = w >> 2, wn = w & 3;
    float acc[4][4][4];
#pragma unroll
    for (int mt = 0; mt < 4; mt++)
#pragma unroll
        for (int nt = 0; nt < 4; nt++)
#pragma unroll
            for (int q = 0; q < 4; q++) acc[mt][nt][q] = 0.f;

    const unsigned psu = (unsigned)__cvta_generic_to_shared(ps);
    const unsigned aAddr = psu + (wm * 64 + (lane & 15)) * PCHB;
    const unsigned axor = lane & 7;
    const unsigned acs  = lane >> 4;
    const int bn = wn * 32 + (lane & 7) + ((lane >> 4) << 3);
    const unsigned bAddr = psu + PTILE + bn * PCHB;
    const unsigned bcs  = (lane >> 3) & 1;

    const uint4* srcA = (const uint4*)(g_embB + (size_t)m0 * KP);
    const uint4* srcW = (const uint4*)(g_WB[d] + (size_t)n0 * KP);

#pragma unroll
    for (int pass = 0; pass < 2; pass++) {
        const int nch = pass ? 18 : 20;
        const int cbase = pass * 20;
        if (pass) __syncthreads();
        for (int i = tid; i < 128 * nch; i += 256) {
            int row = i / nch, ch = i % nch;
            unsigned off = row * PCHB + (((unsigned)ch ^ (row & 7)) << 4);
            *(uint4*)(ps + off)         = srcA[row * 38 + cbase + ch];
            *(uint4*)(ps + PTILE + off) = srcW[row * 38 + cbase + ch];
        }
        __syncthreads();
        const int nkt = pass ? 9 : 10;
        for (int kt = 0; kt < nkt; kt++) {
            unsigned a[4][4];
            unsigned aoff = ((((unsigned)(2 * kt) + acs) ^ axor) << 4);
#pragma unroll
            for (int mt = 0; mt < 4; mt++)
                ldsm4(aAddr + mt * 16 * PCHB + aoff, a[mt][0], a[mt][1], a[mt][2], a[mt][3]);
            unsigned bq[2][4];
            unsigned boff = ((((unsigned)(2 * kt) + bcs) ^ axor) << 4);
#pragma unroll
            for (int nb = 0; nb < 2; nb++)
                ldsm4(bAddr + nb * 16 * PCHB + boff, bq[nb][0], bq[nb][1], bq[nb][2], bq[nb][3]);
#pragma unroll
            for (int mt = 0; mt < 4; mt++) {
                mma16816(acc[mt][0], a[mt][0], a[mt][1], a[mt][2], a[mt][3], bq[0][0], bq[0][1]);
                mma16816(acc[mt][1], a[mt][0], a[mt][1], a[mt][2], a[mt][3], bq[0][2], bq[0][3]);
                mma16816(acc[mt][2], a[mt][0], a[mt][1], a[mt][2], a[mt][3], bq[1][0], bq[1][1]);
                mma16816(acc[mt][3], a[mt][0], a[mt][1], a[mt][2], a[mt][3], bq[1][2], bq[1][3]);
            }
        }
    }

#pragma unroll
    for (int mt = 0; mt < 4; mt++) {
        int r = m0 + wm * 64 + mt * 16 + (lane >> 2);
#pragma unroll
        for (int nt = 0; nt < 4; nt++) {
            int cl = wn * 32 + nt * 8 + 2 * (lane & 3);
            float b0 = bsh[cl], b1 = bsh[cl + 1];
            float* dst = &g_projP[d][(size_t)r * G4 + n0 + cl];
            if (r < V_)
                *(float2*)dst = make_float2(acc[mt][nt][0] + b0, acc[mt][nt][1] + b1);
            if (r + 8 < V_)
                *(float2*)(dst + 8 * G4) = make_float2(acc[mt][nt][2] + b0, acc[mt][nt][3] + b1);
        }
    }
}

// ---- BiLSTM via transposed HMMA (W in regs) + proj prefetch: grid (32,2) ----
__global__ void __launch_bounds__(512) k_lstm(const int* __restrict__ sent,
                                              const int* __restrict__ seqlen) {
    const int d  = blockIdx.y;
    const int g8 = blockIdx.x * 8;
    __shared__ __align__(16) __nv_bfloat16 hsm[2][H_][8];
    __shared__ int toks[8][T_];
    __shared__ int len[8];
    __shared__ int rws[8];

    const int tid = threadIdx.x;
    const int w = tid >> 5, lane = tid & 31;

    ((ull*)hsm)[tid] = 0ull;
    if (tid < 8) {
        int row = g_perm[g8 + tid];
        rws[tid] = row;
        int L = seqlen[row];
        len[tid] = L < 1 ? 1 : (L > T_ ? T_ : L);
    }
    __syncthreads();
    for (int i = tid; i < 8 * T_; i += 512) {
        int r = i / T_, t = i % T_;
        toks[r][t] = sent[rws[r] * T_ + t];
    }
    __syncthreads();

    const int Lmax = len[7];

    unsigned afr[2][8][4];
    {
        const __nv_bfloat16* WA = g_WA[d];
        int mbase = 32 * w + (lane >> 2);
        int kbase = 2 * (lane & 3);
#pragma unroll
        for (int tt = 0; tt < 2; tt++)
#pragma unroll
            for (int kt = 0; kt < 8; kt++) {
                int m = mbase + 16 * tt;
                int k = 16 * kt + kbase;
                afr[tt][kt][0] = *(const unsigned*)&WA[m * H_ + k];
                afr[tt][kt][1] = *(const unsigned*)&WA[(m + 8) * H_ + k];
                afr[tt][kt][2] = *(const unsigned*)&WA[m * H_ + k + 8];
                afr[tt][kt][3] = *(const unsigned*)&WA[(m + 8) * H_ + k + 8];
            }
    }

    const int r0 = 2 * (lane & 3), r1 = r0 + 1;
    const int u  = 8 * w + (lane >> 2);
    const int len0 = len[r0], len1 = len[r1];
    const size_t row0 = (size_t)rws[r0], row1 = (size_t)rws[r1];
    float c0 = 0.f, c1 = 0.f, h0 = 0.f, h1 = 0.f;

    const float4* __restrict__ projP4 = (const float4*)g_projP[d];
    const unsigned hbase = (unsigned)__cvta_generic_to_shared(&hsm[0][0][0]);
    const unsigned ldsm_off = (lane & 15) * 16;
    const unsigned sts_off = u * 16 + r0 * 2;

    // prefetch proj for t = 0
    float4 pa0, pa1;
    {
        int tt0 = (d == 0) ? 0 : (len0 - 1);
        int tt1 = (d == 0) ? 0 : (len1 - 1);
        pa0 = __ldcg(&projP4[(size_t)toks[r0][tt0] * 128 + u]);
        pa1 = __ldcg(&projP4[(size_t)toks[r1][tt1] * 128 + u]);
    }

    for (int t = 0; t < Lmax; t++) {
        const bool m0 = t < len0, m1 = t < len1;
        // prefetch proj for t+1 (value unused on last iter)
        float4 pn0, pn1;
        {
            int tn = (t + 1 < Lmax) ? t + 1 : 0;
            bool n0 = tn < len0, n1 = tn < len1;
            int tt0 = (d == 0) ? tn : (n0 ? (len0 - 1 - tn) : tn);
            int tt1 = (d == 0) ? tn : (n1 ? (len1 - 1 - tn) : tn);
            pn0 = __ldcg(&projP4[(size_t)toks[r0][tt0] * 128 + u]);
            pn1 = __ldcg(&projP4[(size_t)toks[r1][tt1] * 128 + u]);
        }

        float d0[4] = {0.f, 0.f, 0.f, 0.f};
        float d1[4] = {0.f, 0.f, 0.f, 0.f};
        unsigned hb = hbase + (t & 1) * 2048 + ldsm_off;
#pragma unroll
        for (int kt = 0; kt < 8; kt++) {
            unsigned b0, b1;
            ldsm2t(hb + kt * 256, b0, b1);
            mma16816(d0, afr[0][kt][0], afr[0][kt][1], afr[0][kt][2], afr[0][kt][3], b0, b1);
            mma16816(d1, afr[1][kt][0], afr[1][kt][1], afr[1][kt][2], afr[1][kt][3], b0, b1);
        }

        {
            float xi = d0[0] + pa0.x, xf = d0[2] + pa0.y;
            float xg = d1[0] + pa0.z, xo = d1[2] + pa0.w;
            float si = sig_mufu(xi), sf = sig_mufu(xf), so = sig_mufu(xo);
            float tg = tanh_mufu(xg);
            float cn = sf * c0 + si * tg;
            float hn = so * tanh_mufu(cn);
            c0 = m0 ? cn : c0;
            h0 = m0 ? hn : h0;
        }
        {
            float xi = d0[1] + pa1.x, xf = d0[3] + pa1.y;
            float xg = d1[1] + pa1.z, xo = d1[3] + pa1.w;
            float si = sig_mufu(xi), sf = sig_mufu(xf), so = sig_mufu(xo);
            float tg = tanh_mufu(xg);
            float cn = sf * c1 + si * tg;
            float hn = so * tanh_mufu(cn);
            c1 = m1 ? cn : c1;
            h1 = m1 ? hn : h1;
        }
        unsigned hpack = (unsigned)__bfloat16_as_ushort(__float2bfloat16(h0)) |
                         ((unsigned)__bfloat16_as_ushort(__float2bfloat16(h1)) << 16);
        *(unsigned*)((char*)hsm + ((t + 1) & 1) * 2048 + sts_off) = hpack;
        if (m0) {
            int op = (d == 0) ? t : (len0 - 1 - t);
            g_hbuf[(row0 * T_ + op) * H2_ + d * H_ + u] = __float2bfloat16(h0);
        }
        if (m1) {
            int op = (d == 0) ? t : (len1 - 1 - t);
            g_hbuf[(row1 * T_ + op) * H2_ + d * H_ + u] = __float2bfloat16(h1);
        }
        pa0 = pn0;
        pa1 = pn1;
        __syncthreads();
    }
}

// ---- FC: feats = hbuf(bf16) @ W_fc^T; 32 positions/block, warp per tag ----
__global__ void __launch_bounds__(416) k_fc(const float* __restrict__ Wfc) {
    __shared__ uint4 hsm[32][33];
    __shared__ float Wsh[NT_][256];
    int tid = threadIdx.x;
    size_t base = (size_t)blockIdx.x * 32;
    for (int i = tid; i < 32 * 32; i += 416) {
        int p = i >> 5, c = i & 31;
        hsm[p][c] = ((const uint4*)g_hbuf)[(base + p) * 32 + c];
    }
    for (int i = tid; i < NT_ * H2_; i += 416) Wsh[i >> 8][i & 255] = Wfc[i];
    __syncthreads();
    int w = tid >> 5, lane = tid & 31;
    if (w < NT_) {
        float acc = 0.f;
        const float* wr = Wsh[w];
#pragma unroll 4
        for (int c = 0; c < 32; c++) {
            uint4 v = hsm[lane][c];
            const unsigned* vu = (const unsigned*)&v;
#pragma unroll
            for (int e = 0; e < 4; e++) {
                unsigned uu = vu[e];
                float f0 = __uint_as_float(uu << 16);
                float f1 = __uint_as_float(uu & 0xFFFF0000u);
                acc = fmaf(f0, wr[c * 8 + 2 * e], acc);
                acc = fmaf(f1, wr[c * 8 + 2 * e + 1], acc);
            }
        }
        g_feats[(base + lane) * NT_ + w] = acc;
    }
}

// ---- CRF: exp-factorized logsumexp, warp per sequence ----
__global__ void __launch_bounds__(128) k_crf(const float* __restrict__ trans,
                                             const int* __restrict__ tags,
                                             const float* __restrict__ bfc) {
    __shared__ float tr[NT_ * NT_];
    __shared__ float bsh[16];
    int tid = threadIdx.x;
    if (tid < NT_ * NT_) tr[tid] = trans[tid];
    if (tid < NT_) bsh[tid] = bfc[tid];
    __syncthreads();
    int warp = tid >> 5, lane = tid & 31;
    int b = blockIdx.x * 4 + warp;
    bool valid = lane < NT_;
    int jj = valid ? lane : 0;
    float Ej[NT_];
#pragma unroll
    for (int i = 0; i < NT_; i++) Ej[i] = valid ? __expf(tr[jj * NT_ + i]) : 0.f;
    float bj = bsh[jj];
    float alpha = valid ? ((jj == START_) ? 0.f : NEGV) : -3e38f;
    const float* __restrict__ fF = &g_feats[(size_t)b * T_ * NT_];

    for (int t = 0; t < T_; t++) {
        float ft = valid ? (fF[t * NT_ + jj] + bj) : 0.f;
        float am = alpha;
#pragma unroll
        for (int off = 16; off; off >>= 1) am = fmaxf(am, __shfl_xor_sync(0xffffffffu, am, off));
        float ea = valid ? __expf(alpha - am) : 0.f;
        float s = 0.f;
#pragma unroll
        for (int i = 0; i < NT_; i++)
            s = fmaf(__shfl_sync(0xffffffffu, ea, i), Ej[i], s);
        float an = am + __logf(s) + ft;
        if (valid) alpha = an;
    }
    float v = valid ? (alpha + tr[STOP_ * NT_ + jj]) : -3e38f;
    float mm = v;
#pragma unroll
    for (int off = 16; off; off >>= 1) mm = fmaxf(mm, __shfl_xor_sync(0xffffffffu, mm, off));
    float se = valid ? __expf(v - mm) : 0.f;
#pragma unroll
    for (int off = 16; off; off >>= 1) se += __shfl_xor_sync(0xffffffffu, se, off);
    float fwd = mm + __logf(se);

    float gold = 0.f;
    for (int t = lane; t < T_; t += 32) {
        int tg = tags[b * T_ + t];
        int tp = (t == 0) ? START_ : tags[b * T_ + t - 1];
        gold += tr[tg * NT_ + tp] + fF[t * NT_ + tg] + bsh[tg];
    }
#pragma unroll
    for (int off = 16; off; off >>= 1) gold += __shfl_xor_sync(0xffffffffu, gold, off);
    if (lane == 0) {
        int tlast = tags[b * T_ + T_ - 1];
        gold += tr[STOP_ * NT_ + tlast];
        g_nll[b] = fwd - gold;
    }
}

__global__ void k_reduce(float* __restrict__ out) {
    __shared__ float sm[256];
    int tid = threadIdx.x;
    sm[tid] = g_nll[tid];
    __syncthreads();
    for (int s = 128; s > 0; s >>= 1) {
        if (tid < s) sm[tid] += sm[tid + s];
        __syncthreads();
    }
    if (tid == 0) out[0] = sm[0] * (1.f / (float)B_);
}

extern "C" void kernel_launch(void* const* d_in, const int* in_sizes, int n_in,
                              void* d_out, int out_size) {
    const int*   sentence  = (const int*)d_in[0];
    const int*   seq_len   = (const int*)d_in[1];
    const int*   tags      = (const int*)d_in[2];
    const float* embedding = (const float*)d_in[3];
    const float* W_ih_f    = (const float*)d_in[4];
    const float* W_hh_f    = (const float*)d_in[5];
    const float* b_f       = (const float*)d_in[6];
    const float* W_ih_b    = (const float*)d_in[7];
    const float* W_hh_b    = (const float*)d_in[8];
    const float* b_b       = (const float*)d_in[9];
    const float* W_fc      = (const float*)d_in[10];
    const float* b_fc      = (const float*)d_in[11];
    const float* trans     = (const float*)d_in[12];

    cudaFuncSetAttribute(k_projmm, cudaFuncAttributeMaxDynamicSharedMemorySize, PSMEM);

    int packBlocks = (int)(((size_t)VPAD * KP + 255) / 256);
    k_sortpack<<<257 + packBlocks, 256>>>(seq_len, embedding,
                                          W_ih_f, W_ih_b, W_hh_f, W_hh_b);   // 0
    dim3 gpm(VPAD / 128, 4, 2);
    k_projmm<<<gpm, 256, PSMEM>>>(b_f, b_b);                                 // 1
    dim3 gl(32, 2);
    k_lstm<<<gl, 512>>>(sentence, seq_len);                                  // 2
    k_fc<<<(B_ * T_) / 32, 416>>>(W_fc);                                     // 3 <- likely profiled
    k_crf<<<B_ / 4, 128>>>(trans, tags, b_fc);                               // 4
    k_reduce<<<1, 256>>>((float*)d_out);                                     // 5
}

// round 17
// speedup vs baseline: 1.5337x; 1.0215x over previous
#include <cuda_runtime.h>
#include <cuda_bf16.h>

#define B_    256
#define T_    192
#define E_    300
#define H_    128
#define G4    512
#define V_    11626
#define NT_   13
#define H2_   256
#define NEGV  (-10000.0f)
#define START_ 0
#define STOP_  10

#define VPAD  11648           // 91 * 128
#define KP    304             // K padded to 16
#define PCHB  384             // projmm smem row pitch bytes (24 chunks)
#define PTILE 49152           // 128 * PCHB
#define PSMEM (2 * PTILE + 512)

typedef unsigned long long ull;

// ---- device scratch (allocations are forbidden) ----
__device__ float          g_projP[2][(size_t)V_ * G4];   // unit-major: col = 4u+gate
__device__ __nv_bfloat16  g_WA[2][G4 * H_];              // lstm A-matrix [m'][k]
__device__ __nv_bfloat16  g_WB[2][G4 * KP];              // proj B-matrix [c'][k]
__device__ __nv_bfloat16  g_embB[(size_t)VPAD * KP];     // emb bf16 padded
__device__ __nv_bfloat16  g_hbuf[(size_t)B_ * T_ * H2_];
__device__ float          g_feats[(size_t)B_ * T_ * NT_];
__device__ float          g_nll[B_];
__device__ int            g_perm[B_];

__device__ __forceinline__ float tanh_mufu(float x) {
    float r; asm("tanh.approx.f32 %0, %1;" : "=f"(r) : "f"(x)); return r;
}
__device__ __forceinline__ float sig_mufu(float x) {
    return fmaf(tanh_mufu(0.5f * x), 0.5f, 0.5f);
}

// ---- tensor-core helpers ----
__device__ __forceinline__ void ldsm4(unsigned addr, unsigned& r0, unsigned& r1,
                                      unsigned& r2, unsigned& r3) {
    asm volatile("ldmatrix.sync.aligned.m8n8.x4.shared.b16 {%0,%1,%2,%3}, [%4];"
                 : "=r"(r0), "=r"(r1), "=r"(r2), "=r"(r3) : "r"(addr));
}
__device__ __forceinline__ void ldsm2t(unsigned addr, unsigned& b0, unsigned& b1) {
    asm volatile("ldmatrix.sync.aligned.m8n8.x2.trans.shared.b16 {%0,%1}, [%2];"
                 : "=r"(b0), "=r"(b1) : "r"(addr));
}
__device__ __forceinline__ void mma16816(float* d, unsigned a0, unsigned a1,
                                         unsigned a2, unsigned a3,
                                         unsigned b0, unsigned b1) {
    asm volatile("mma.sync.aligned.m16n8k16.row.col.f32.bf16.bf16.f32 "
                 "{%0,%1,%2,%3}, {%4,%5,%6,%7}, {%8,%9}, {%0,%1,%2,%3};"
                 : "+f"(d[0]), "+f"(d[1]), "+f"(d[2]), "+f"(d[3])
                 : "r"(a0), "r"(a1), "r"(a2), "r"(a3), "r"(b0), "r"(b1));
}

// ---- merged: block 0 sorts; blocks 1..256 zero hbuf; blocks 257+ pack ----
__global__ void __launch_bounds__(256) k_sortpack(const int* __restrict__ seqlen,
                          const float* __restrict__ emb,
                          const float* __restrict__ Wihf, const float* __restrict__ Wihb,
                          const float* __restrict__ Whhf, const float* __restrict__ Whhb) {
    if (blockIdx.x == 0) {
        __shared__ int len_sh[B_];
        int t = threadIdx.x;
        int L = seqlen[t];
        L = L < 1 ? 1 : (L > T_ ? T_ : L);
        len_sh[t] = L;
        __syncthreads();
        int rank = 0;
        for (int i = 0; i < B_; i++) {
            int Li = len_sh[i];
            rank += (Li < L) || (Li == L && i < t);
        }
        g_perm[rank] = t;
    } else if (blockIdx.x <= 256) {
        size_t nh = (size_t)B_ * T_ * H2_ * 2 / 16;      // uint4 count
        size_t stride = (size_t)256 * 256;
        size_t i = (size_t)(blockIdx.x - 1) * 256 + threadIdx.x;
        uint4 zu = make_uint4(0u, 0u, 0u, 0u);
        for (; i < nh; i += stride) ((uint4*)g_hbuf)[i] = zu;
    } else {
        size_t idx = (size_t)(blockIdx.x - 257) * 256 + threadIdx.x;
        if (idx < (size_t)VPAD * KP) {
            int v = (int)(idx / KP), e = (int)(idx % KP);
            float x = (v < V_ && e < E_) ? emb[(size_t)v * E_ + e] : 0.f;
            g_embB[idx] = __float2bfloat16(x);
        }
        if (idx < 2 * G4 * KP) {
            int d = (int)(idx / (G4 * KP)), rem = (int)(idx % (G4 * KP));
            int c = rem / KP, k = rem % KP;
            const float* W = d ? Wihb : Wihf;
            int orow = (c & 3) * 128 + (c >> 2);
            g_WB[d][c * KP + k] = __float2bfloat16(k < E_ ? W[orow * E_ + k] : 0.f);
        }
        if (idx < 2 * G4 * H_) {
            int d = (int)(idx / (G4 * H_)), rem = (int)(idx % (G4 * H_));
            int n = rem >> 7, k = rem & 127;
            const float* W = d ? Whhb : Whhf;
            int gate = n >> 7, u = n & 127;
            int mp = 32 * (u >> 3) + (u & 7) + 8 * gate;
            g_WA[d][mp * H_ + k] = __float2bfloat16(W[n * H_ + k]);
        }
    }
}

// ---- proj GEMM via HMMA, K split into 2 passes (96 KB smem -> 2 CTA/SM) ----
__global__ void __launch_bounds__(256) k_projmm(const float* __restrict__ bf,
                                                const float* __restrict__ bb) {
    extern __shared__ __align__(16) char ps[];
    const int d  = blockIdx.z;
    const int m0 = blockIdx.x * 128;
    const int n0 = blockIdx.y * 128;
    const float* bias = d ? bb : bf;
    const int tid = threadIdx.x;
    const int w = tid >> 5, lane = tid & 31;
    float* bsh = (float*)(ps + 2 * PTILE);

    if (tid < 128) {
        int c = n0 + tid;
        bsh[tid] = bias[(c & 3) * 128 + (c >> 2)];
    }

    const int wm = w >> 2, wn = w & 3;
    float acc[4][4][4];
#pragma unroll
    for (int mt = 0; mt < 4; mt++)
#pragma unroll
        for (int nt = 0; nt < 4; nt++)
#pragma unroll
            for (int q = 0; q < 4; q++) acc[mt][nt][q] = 0.f;

    const unsigned psu = (unsigned)__cvta_generic_to_shared(ps);
    const unsigned aAddr = psu + (wm * 64 + (lane & 15)) * PCHB;
    const unsigned axor = lane & 7;
    const unsigned acs  = lane >> 4;
    const int bn = wn * 32 + (lane & 7) + ((lane >> 4) << 3);
    const unsigned bAddr = psu + PTILE + bn * PCHB;
    const unsigned bcs  = (lane >> 3) & 1;

    const uint4* srcA = (const uint4*)(g_embB + (size_t)m0 * KP);
    const uint4* srcW = (const uint4*)(g_WB[d] + (size_t)n0 * KP);

#pragma unroll
    for (int pass = 0; pass < 2; pass++) {
        const int nch = pass ? 18 : 20;
        const int cbase = pass * 20;
        if (pass) __syncthreads();
        for (int i = tid; i < 128 * nch; i += 256) {
            int row = i / nch, ch = i % nch;
            unsigned off = row * PCHB + (((unsigned)ch ^ (row & 7)) << 4);
            *(uint4*)(ps + off)         = srcA[row * 38 + cbase + ch];
            *(uint4*)(ps + PTILE + off) = srcW[row * 38 + cbase + ch];
        }
        __syncthreads();
        const int nkt = pass ? 9 : 10;
        for (int kt = 0; kt < nkt; kt++) {
            unsigned a[4][4];
            unsigned aoff = ((((unsigned)(2 * kt) + acs) ^ axor) << 4);
#pragma unroll
            for (int mt = 0; mt < 4; mt++)
                ldsm4(aAddr + mt * 16 * PCHB + aoff, a[mt][0], a[mt][1], a[mt][2], a[mt][3]);
            unsigned bq[2][4];
            unsigned boff = ((((unsigned)(2 * kt) + bcs) ^ axor) << 4);
#pragma unroll
            for (int nb = 0; nb < 2; nb++)
                ldsm4(bAddr + nb * 16 * PCHB + boff, bq[nb][0], bq[nb][1], bq[nb][2], bq[nb][3]);
#pragma unroll
            for (int mt = 0; mt < 4; mt++) {
                mma16816(acc[mt][0], a[mt][0], a[mt][1], a[mt][2], a[mt][3], bq[0][0], bq[0][1]);
                mma16816(acc[mt][1], a[mt][0], a[mt][1], a[mt][2], a[mt][3], bq[0][2], bq[0][3]);
                mma16816(acc[mt][2], a[mt][0], a[mt][1], a[mt][2], a[mt][3], bq[1][0], bq[1][1]);
                mma16816(acc[mt][3], a[mt][0], a[mt][1], a[mt][2], a[mt][3], bq[1][2], bq[1][3]);
            }
        }
    }

#pragma unroll
    for (int mt = 0; mt < 4; mt++) {
        int r = m0 + wm * 64 + mt * 16 + (lane >> 2);
#pragma unroll
        for (int nt = 0; nt < 4; nt++) {
            int cl = wn * 32 + nt * 8 + 2 * (lane & 3);
            float b0 = bsh[cl], b1 = bsh[cl + 1];
            float* dst = &g_projP[d][(size_t)r * G4 + n0 + cl];
            if (r < V_)
                *(float2*)dst = make_float2(acc[mt][nt][0] + b0, acc[mt][nt][1] + b1);
            if (r + 8 < V_)
                *(float2*)(dst + 8 * G4) = make_float2(acc[mt][nt][2] + b0, acc[mt][nt][3] + b1);
        }
    }
}

// ---- BiLSTM via transposed HMMA (W in regs) + proj prefetch: grid (32,2) ----
__global__ void __launch_bounds__(512) k_lstm(const int* __restrict__ sent,
                                              const int* __restrict__ seqlen) {
    const int d  = blockIdx.y;
    const int g8 = blockIdx.x * 8;
    __shared__ __align__(16) __nv_bfloat16 hsm[2][H_][8];
    __shared__ int toks[8][T_];
    __shared__ int len[8];
    __shared__ int rws[8];

    const int tid = threadIdx.x;
    const int w = tid >> 5, lane = tid & 31;

    ((ull*)hsm)[tid] = 0ull;
    if (tid < 8) {
        int row = g_perm[g8 + tid];
        rws[tid] = row;
        int L = seqlen[row];
        len[tid] = L < 1 ? 1 : (L > T_ ? T_ : L);
    }
    __syncthreads();
    for (int i = tid; i < 8 * T_; i += 512) {
        int r = i / T_, t = i % T_;
        toks[r][t] = sent[rws[r] * T_ + t];
    }
    __syncthreads();

    const int Lmax = len[7];

    unsigned afr[2][8][4];
    {
        const __nv_bfloat16* WA = g_WA[d];
        int mbase = 32 * w + (lane >> 2);
        int kbase = 2 * (lane & 3);
#pragma unroll
        for (int tt = 0; tt < 2; tt++)
#pragma unroll
            for (int kt = 0; kt < 8; kt++) {
                int m = mbase + 16 * tt;
                int k = 16 * kt + kbase;
                afr[tt][kt][0] = *(const unsigned*)&WA[m * H_ + k];
                afr[tt][kt][1] = *(const unsigned*)&WA[(m + 8) * H_ + k];
                afr[tt][kt][2] = *(const unsigned*)&WA[m * H_ + k + 8];
                afr[tt][kt][3] = *(const unsigned*)&WA[(m + 8) * H_ + k + 8];
            }
    }

    const int r0 = 2 * (lane & 3), r1 = r0 + 1;
    const int u  = 8 * w + (lane >> 2);
    const int len0 = len[r0], len1 = len[r1];
    const size_t row0 = (size_t)rws[r0], row1 = (size_t)rws[r1];
    float c0 = 0.f, c1 = 0.f, h0 = 0.f, h1 = 0.f;

    const float4* __restrict__ projP4 = (const float4*)g_projP[d];
    const unsigned hbase = (unsigned)__cvta_generic_to_shared(&hsm[0][0][0]);
    const unsigned ldsm_off = (lane & 15) * 16;
    const unsigned sts_off = u * 16 + r0 * 2;

    // prefetch proj for t = 0
    float4 pa0, pa1;
    {
        int tt0 = (d == 0) ? 0 : (len0 - 1);
        int tt1 = (d == 0) ? 0 : (len1 - 1);
        pa0 = __ldcg(&projP4[(size_t)toks[r0][tt0] * 128 + u]);
        pa1 = __ldcg(&projP4[(size_t)toks[r1][tt1] * 128 + u]);
    }

    for (int t = 0; t < Lmax; t++) {
        const bool m0 = t < len0, m1 = t < len1;
        // prefetch proj for t+1 (value unused on last iter)
        float4 pn0, pn1;
        {
            int tn = (t + 1 < Lmax) ? t + 1 : 0;
            bool n0 = tn < len0, n1 = tn < len1;
            int tt0 = (d == 0) ? tn : (n0 ? (len0 - 1 - tn) : tn);
            int tt1 = (d == 0) ? tn : (n1 ? (len1 - 1 - tn) : tn);
            pn0 = __ldcg(&projP4[(size_t)toks[r0][tt0] * 128 + u]);
            pn1 = __ldcg(&projP4[(size_t)toks[r1][tt1] * 128 + u]);
        }

        float d0[4] = {0.f, 0.f, 0.f, 0.f};
        float d1[4] = {0.f, 0.f, 0.f, 0.f};
        unsigned hb = hbase + (t & 1) * 2048 + ldsm_off;
#pragma unroll
        for (int kt = 0; kt < 8; kt++) {
            unsigned b0, b1;
            ldsm2t(hb + kt * 256, b0, b1);
            mma16816(d0, afr[0][kt][0], afr[0][kt][1], afr[0][kt][2], afr[0][kt][3], b0, b1);
            mma16816(d1, afr[1][kt][0], afr[1][kt][1], afr[1][kt][2], afr[1][kt][3], b0, b1);
        }

        {
            float xi = d0[0] + pa0.x, xf = d0[2] + pa0.y;
            float xg = d1[0] + pa0.z, xo = d1[2] + pa0.w;
            float si = sig_mufu(xi), sf = sig_mufu(xf), so = sig_mufu(xo);
            float tg = tanh_mufu(xg);
            float cn = sf * c0 + si * tg;
            float hn = so * tanh_mufu(cn);
            c0 = m0 ? cn : c0;
            h0 = m0 ? hn : h0;
        }
        {
            float xi = d0[1] + pa1.x, xf = d0[3] + pa1.y;
            float xg = d1[1] + pa1.z, xo = d1[3] + pa1.w;
            float si = sig_mufu(xi), sf = sig_mufu(xf), so = sig_mufu(xo);
            float tg = tanh_mufu(xg);
            float cn = sf * c1 + si * tg;
            float hn = so * tanh_mufu(cn);
            c1 = m1 ? cn : c1;
            h1 = m1 ? hn : h1;
        }
        unsigned hpack = (unsigned)__bfloat16_as_ushort(__float2bfloat16(h0)) |
                         ((unsigned)__bfloat16_as_ushort(__float2bfloat16(h1)) << 16);
        *(unsigned*)((char*)hsm + ((t + 1) & 1) * 2048 + sts_off) = hpack;
        if (m0) {
            int op = (d == 0) ? t : (len0 - 1 - t);
            g_hbuf[(row0 * T_ + op) * H2_ + d * H_ + u] = __float2bfloat16(h0);
        }
        if (m1) {
            int op = (d == 0) ? t : (len1 - 1 - t);
            g_hbuf[(row1 * T_ + op) * H2_ + d * H_ + u] = __float2bfloat16(h1);
        }
        pa0 = pn0;
        pa1 = pn1;
        __syncthreads();
    }
}

// ---- FC: feats = hbuf(bf16) @ W_fc^T; 32 positions/block, warp per tag ----
__global__ void __launch_bounds__(416) k_fc(const float* __restrict__ Wfc) {
    __shared__ uint4 hsm[32][33];
    __shared__ float Wsh[NT_][256];
    int tid = threadIdx.x;
    size_t base = (size_t)blockIdx.x * 32;
    for (int i = tid; i < 32 * 32; i += 416) {
        int p = i >> 5, c = i & 31;
        hsm[p][c] = ((const uint4*)g_hbuf)[(base + p) * 32 + c];
    }
    for (int i = tid; i < NT_ * H2_; i += 416) Wsh[i >> 8][i & 255] = Wfc[i];
    __syncthreads();
    int w = tid >> 5, lane = tid & 31;
    if (w < NT_) {
        float acc = 0.f;
        const float* wr = Wsh[w];
#pragma unroll 4
        for (int c = 0; c < 32; c++) {
            uint4 v = hsm[lane][c];
            const unsigned* vu = (const unsigned*)&v;
#pragma unroll
            for (int e = 0; e < 4; e++) {
                unsigned uu = vu[e];
                float f0 = __uint_as_float(uu << 16);
                float f1 = __uint_as_float(uu & 0xFFFF0000u);
                acc = fmaf(f0, wr[c * 8 + 2 * e], acc);
                acc = fmaf(f1, wr[c * 8 + 2 * e + 1], acc);
            }
        }
        g_feats[(base + lane) * NT_ + w] = acc;
    }
}

// ---- CRF: exp-factorized logsumexp, 2-shfl shift (validated in R15) ----
__global__ void __launch_bounds__(128) k_crf(const float* __restrict__ trans,
                                             const int* __restrict__ tags,
                                             const float* __restrict__ bfc) {
    __shared__ float tr[NT_ * NT_];
    __shared__ float bsh[16];
    int tid = threadIdx.x;
    if (tid < NT_ * NT_) tr[tid] = trans[tid];
    if (tid < NT_) bsh[tid] = bfc[tid];
    __syncthreads();
    int warp = tid >> 5, lane = tid & 31;
    int b = blockIdx.x * 4 + warp;
    bool valid = lane < NT_;
    int jj = valid ? lane : 0;
    float Ej[NT_];
#pragma unroll
    for (int i = 0; i < NT_; i++) Ej[i] = valid ? __expf(tr[jj * NT_ + i]) : 0.f;
    float bj = bsh[jj];
    float alpha = valid ? ((jj == START_) ? 0.f : NEGV) : -3e38f;
    const float* __restrict__ fF = &g_feats[(size_t)b * T_ * NT_];

    for (int t = 0; t < T_; t++) {
        float ft = valid ? (fF[t * NT_ + jj] + bj) : 0.f;
        // shift = max(alpha_0, alpha_1): lse is shift-invariant; spread bounded
        float sA = __shfl_sync(0xffffffffu, alpha, 0);
        float sB = __shfl_sync(0xffffffffu, alpha, 1);
        float shift = fmaxf(sA, sB);
        float ea = valid ? __expf(alpha - shift) : 0.f;
        float s = 0.f;
#pragma unroll
        for (int i = 0; i < NT_; i++)
            s = fmaf(__shfl_sync(0xffffffffu, ea, i), Ej[i], s);
        float an = shift + __logf(s) + ft;
        if (valid) alpha = an;
    }
    float v = valid ? (alpha + tr[STOP_ * NT_ + jj]) : -3e38f;
    float mm = v;
#pragma unroll
    for (int off = 16; off; off >>= 1) mm = fmaxf(mm, __shfl_xor_sync(0xffffffffu, mm, off));
    float se = valid ? __expf(v - mm) : 0.f;
#pragma unroll
    for (int off = 16; off; off >>= 1) se += __shfl_xor_sync(0xffffffffu, se, off);
    float fwd = mm + __logf(se);

    float gold = 0.f;
    for (int t = lane; t < T_; t += 32) {
        int tg = tags[b * T_ + t];
        int tp = (t == 0) ? START_ : tags[b * T_ + t - 1];
        gold += tr[tg * NT_ + tp] + fF[t * NT_ + tg] + bsh[tg];
    }
#pragma unroll
    for (int off = 16; off; off >>= 1) gold += __shfl_xor_sync(0xffffffffu, gold, off);
    if (lane == 0) {
        int tlast = tags[b * T_ + T_ - 1];
        gold += tr[STOP_ * NT_ + tlast];
        g_nll[b] = fwd - gold;
    }
}

__global__ void k_reduce(float* __restrict__ out) {
    __shared__ float sm[256];
    int tid = threadIdx.x;
    sm[tid] = g_nll[tid];
    __syncthreads();
    for (int s = 128; s > 0; s >>= 1) {
        if (tid < s) sm[tid] += sm[tid + s];
        __syncthreads();
    }
    if (tid == 0) out[0] = sm[0] * (1.f / (float)B_);
}

extern "C" void kernel_launch(void* const* d_in, const int* in_sizes, int n_in,
                              void* d_out, int out_size) {
    const int*   sentence  = (const int*)d_in[0];
    const int*   seq_len   = (const int*)d_in[1];
    const int*   tags      = (const int*)d_in[2];
    const float* embedding = (const float*)d_in[3];
    const float* W_ih_f    = (const float*)d_in[4];
    const float* W_hh_f    = (const float*)d_in[5];
    const float* b_f       = (const float*)d_in[6];
    const float* W_ih_b    = (const float*)d_in[7];
    const float* W_hh_b    = (const float*)d_in[8];
    const float* b_b       = (const float*)d_in[9];
    const float* W_fc      = (const float*)d_in[10];
    const float* b_fc      = (const float*)d_in[11];
    const float* trans     = (const float*)d_in[12];

    cudaFuncSetAttribute(k_projmm, cudaFuncAttributeMaxDynamicSharedMemorySize, PSMEM);

    int packBlocks = (int)(((size_t)VPAD * KP + 255) / 256);
    k_sortpack<<<257 + packBlocks, 256>>>(seq_len, embedding,
                                          W_ih_f, W_ih_b, W_hh_f, W_hh_b);   // 0
    dim3 gpm(VPAD / 128, 4, 2);
    k_projmm<<<gpm, 256, PSMEM>>>(b_f, b_b);                                 // 1
    dim3 gl(32, 2);
    k_lstm<<<gl, 512>>>(sentence, seq_len);                                  // 2
    k_fc<<<(B_ * T_) / 32, 416>>>(W_fc);                                     // 3
    k_crf<<<B_ / 4, 128>>>(trans, tags, b_fc);                               // 4
    k_reduce<<<1, 256>>>((float*)d_out);                                     // 5
}